// round 7
// baseline (speedup 1.0000x reference)
#include <cuda_runtime.h>
#include <cstddef>

// BranchRoute single-pass. hot_i = sigmoid(logit_i) > 0.5  <=>  logit_i > 0.
// 8 rows/block, loads front-batched (MLP=8/warp), 16-value value-splitting
// butterfly (16 shfls), then ONE barrier: every warp redundantly reduces the
// 8x16 smem partials and ballots its own flag mask, so warps proceed to their
// store bursts independently (no warp-0 serialization, no second barrier).

constexpr int D       = 1024;
constexpr int THREADS = 256;    // 256 * 4 floats = 1024 = D
constexpr int ROWS    = 8;

__global__ __launch_bounds__(THREADS) void branch_route_kernel(
    const float* __restrict__ x,
    const float* __restrict__ Wg,    // [D, 2]: Wg[k*2 + branch]
    const float* __restrict__ bg,    // [2]
    float* __restrict__ out,         // [3, N, D]
    int n_tokens)
{
    const int t    = threadIdx.x;
    const int lane = t & 31;
    const int wid  = t >> 5;

    // Gate weights for dims 4t..4t+3, register-resident (L2-hit after wave 1).
    const float4* Wg4 = reinterpret_cast<const float4*>(Wg);
    const float4 w01 = __ldg(Wg4 + 2 * t);
    const float4 w23 = __ldg(Wg4 + 2 * t + 1);
    const float  b0  = __ldg(&bg[0]);
    const float  b1  = __ldg(&bg[1]);

    const float4* xv     = reinterpret_cast<const float4*>(x);
    float4*       outv   = reinterpret_cast<float4*>(out);
    const size_t  plane4 = (size_t)n_tokens * (D / 4);
    const size_t  base   = (size_t)blockIdx.x * ROWS * (D / 4) + t;

    // ---- Phase 1: front-batched loads (8 independent LDG.128 in flight) ----
    float4 v[ROWS];
    #pragma unroll
    for (int r = 0; r < ROWS; r++)
        v[r] = __ldcs(xv + base + (size_t)r * (D / 4));

    // ---- Phase 2: per-thread partial dots: 16 values (8 rows x 2 branches) ----
    float s[16];
    #pragma unroll
    for (int r = 0; r < ROWS; r++) {
        s[2*r]   = v[r].x * w01.x + v[r].y * w01.z + v[r].z * w23.x + v[r].w * w23.z;
        s[2*r+1] = v[r].x * w01.y + v[r].y * w01.w + v[r].z * w23.y + v[r].w * w23.w;
    }

    // ---- Phase 3: value-splitting butterfly: 16 values in 16 shfls total ----
    // Lane l ends holding the warp total of value v = (l>>1)&15.
    #define LVL(O, V)                                                          \
    {                                                                          \
        const bool up = (lane & (O)) != 0;                                     \
        _Pragma("unroll")                                                      \
        for (int i = 0; i < (V) / 2; i++) {                                    \
            const float send = up ? s[i] : s[i + (V) / 2];                     \
            const float got  = __shfl_xor_sync(0xFFFFFFFFu, send, (O));        \
            s[i] = (up ? s[i + (V) / 2] : s[i]) + got;                         \
        }                                                                      \
    }
    LVL(16, 16)
    LVL(8,  8)
    LVL(4,  4)
    LVL(2,  2)
    s[0] += __shfl_xor_sync(0xFFFFFFFFu, s[0], 1);   // final pair merge
    #undef LVL

    // ---- Phase 4: ONE barrier; every warp reduces + ballots independently ----
    __shared__ float shp[8][16];       // [warp][value], conflict-free

    if ((lane & 1) == 0) shp[wid][(lane >> 1) & 15] = s[0];
    __syncthreads();

    float tot = 0.0f;
    if (lane < 16) {
        #pragma unroll
        for (int w = 0; w < 8; w++) tot += shp[w][lane];
        tot += (lane & 1) ? b1 : b0;
    }
    // Identical mask in every warp; bit (2r+c) = hot flag of row r, branch c.
    const unsigned m = __ballot_sync(0xFFFFFFFFu, (lane < 16) && (tot > 0.0f));

    // ---- Phase 5: 24 streaming stores from registers ----
    #pragma unroll
    for (int r = 0; r < ROWS; r++) {
        const bool h0 = (m >> (2 * r)) & 1u;
        const bool h1 = (m >> (2 * r + 1)) & 1u;

        const float4 zero = make_float4(0.f, 0.f, 0.f, 0.f);
        const float4 o0 = h0 ? v[r] : zero;
        const float4 o1 = h1 ? v[r] : zero;
        float4 oc;
        oc.x = o0.x + o1.x;
        oc.y = o0.y + o1.y;
        oc.z = o0.z + o1.z;
        oc.w = o0.w + o1.w;

        const size_t idx = base + (size_t)r * (D / 4);
        __stcs(outv + idx,               o0);
        __stcs(outv + plane4 + idx,      o1);
        __stcs(outv + 2 * plane4 + idx,  oc);
    }
}

extern "C" void kernel_launch(void* const* d_in, const int* in_sizes, int n_in,
                              void* d_out, int out_size)
{
    const float* x  = (const float*)d_in[0];   // [N, D]
    const float* Wg = (const float*)d_in[1];   // [D, 2]
    const float* bg = (const float*)d_in[2];   // [2]
    float* out      = (float*)d_out;           // [3, N, D]

    const int n_tokens = in_sizes[0] / D;      // 16384
    const int blocks   = n_tokens / ROWS;      // 2048

    branch_route_kernel<<<blocks, THREADS>>>(x, Wg, bg, out, n_tokens);
}

// round 8
// speedup vs baseline: 1.0202x; 1.0202x over previous
#include <cuda_runtime.h>
#include <cstddef>

// BranchRoute single-pass, occupancy-optimized.
// hot_i = sigmoid(logit_i) > 0.5  <=>  logit_i > 0.
// ROWS=4 per block (v[4]+s[8] -> ~40 regs), __launch_bounds__(256,6) => 6
// blocks/SM = 48 warps (75% occ): other blocks' load/store bursts cover each
// block's shfl/barrier compute phase (R7 showed DRAM% == memory duty cycle).

constexpr int D       = 1024;
constexpr int THREADS = 256;    // 256 * 4 floats = 1024 = D
constexpr int ROWS    = 4;

__global__ __launch_bounds__(THREADS, 6) void branch_route_kernel(
    const float* __restrict__ x,
    const float* __restrict__ Wg,    // [D, 2]: Wg[k*2 + branch]
    const float* __restrict__ bg,    // [2]
    float* __restrict__ out,         // [3, N, D]
    int n_tokens)
{
    const int t    = threadIdx.x;
    const int lane = t & 31;
    const int wid  = t >> 5;

    // Gate weights for dims 4t..4t+3 (L2-hit after first wave).
    const float4* Wg4 = reinterpret_cast<const float4*>(Wg);
    const float4 w01 = __ldg(Wg4 + 2 * t);
    const float4 w23 = __ldg(Wg4 + 2 * t + 1);
    const float  b0  = __ldg(&bg[0]);
    const float  b1  = __ldg(&bg[1]);

    const float4* xv     = reinterpret_cast<const float4*>(x);
    float4*       outv   = reinterpret_cast<float4*>(out);
    const size_t  plane4 = (size_t)n_tokens * (D / 4);
    const size_t  base   = (size_t)blockIdx.x * ROWS * (D / 4) + t;

    // ---- Phase 1: front-batched loads (4 independent LDG.128 in flight) ----
    float4 v[ROWS];
    #pragma unroll
    for (int r = 0; r < ROWS; r++)
        v[r] = __ldcs(xv + base + (size_t)r * (D / 4));

    // ---- Phase 2: partial dots: 8 values (4 rows x 2 branches) ----
    float s[8];
    #pragma unroll
    for (int r = 0; r < ROWS; r++) {
        s[2*r]   = v[r].x * w01.x + v[r].y * w01.z + v[r].z * w23.x + v[r].w * w23.z;
        s[2*r+1] = v[r].x * w01.y + v[r].y * w01.w + v[r].z * w23.y + v[r].w * w23.w;
    }

    // ---- Phase 3: value-splitting butterfly: 8 values, offsets 16/8/4 ----
    // After these levels lane l holds ONE value (index (l>>2)&7), partially
    // summed; two plain butterflies (offsets 2, 1) finish the lane sum.
    #define LVL(O, V)                                                          \
    {                                                                          \
        const bool up = (lane & (O)) != 0;                                     \
        _Pragma("unroll")                                                      \
        for (int i = 0; i < (V) / 2; i++) {                                    \
            const float send = up ? s[i] : s[i + (V) / 2];                     \
            const float got  = __shfl_xor_sync(0xFFFFFFFFu, send, (O));        \
            s[i] = (up ? s[i + (V) / 2] : s[i]) + got;                         \
        }                                                                      \
    }
    LVL(16, 8)
    LVL(8,  4)
    LVL(4,  2)
    s[0] += __shfl_xor_sync(0xFFFFFFFFu, s[0], 2);
    s[0] += __shfl_xor_sync(0xFFFFFFFFu, s[0], 1);
    #undef LVL

    // ---- Phase 4: ONE barrier; every warp reduces + ballots its own mask ----
    __shared__ float shp[8][8];        // [warp][value], conflict-free

    if ((lane & 3) == 0) shp[wid][(lane >> 2) & 7] = s[0];
    __syncthreads();

    float tot = 0.0f;
    if (lane < 8) {
        #pragma unroll
        for (int w = 0; w < 8; w++) tot += shp[w][lane];
        tot += (lane & 1) ? b1 : b0;
    }
    // bit (2r+c) = hot flag of row r, branch c (identical mask in every warp).
    const unsigned m = __ballot_sync(0xFFFFFFFFu, (lane < 8) && (tot > 0.0f));

    // ---- Phase 5: 12 streaming stores from registers ----
    #pragma unroll
    for (int r = 0; r < ROWS; r++) {
        const bool h0 = (m >> (2 * r)) & 1u;
        const bool h1 = (m >> (2 * r + 1)) & 1u;

        const float4 zero = make_float4(0.f, 0.f, 0.f, 0.f);
        const float4 o0 = h0 ? v[r] : zero;
        const float4 o1 = h1 ? v[r] : zero;
        float4 oc;
        oc.x = o0.x + o1.x;
        oc.y = o0.y + o1.y;
        oc.z = o0.z + o1.z;
        oc.w = o0.w + o1.w;

        const size_t idx = base + (size_t)r * (D / 4);
        __stcs(outv + idx,               o0);
        __stcs(outv + plane4 + idx,      o1);
        __stcs(outv + 2 * plane4 + idx,  oc);
    }
}

extern "C" void kernel_launch(void* const* d_in, const int* in_sizes, int n_in,
                              void* d_out, int out_size)
{
    const float* x  = (const float*)d_in[0];   // [N, D]
    const float* Wg = (const float*)d_in[1];   // [D, 2]
    const float* bg = (const float*)d_in[2];   // [2]
    float* out      = (float*)d_out;           // [3, N, D]

    const int n_tokens = in_sizes[0] / D;      // 16384
    const int blocks   = n_tokens / ROWS;      // 4096

    branch_route_kernel<<<blocks, THREADS>>>(x, Wg, bg, out, n_tokens);
}